// round 1
// baseline (speedup 1.0000x reference)
#include <cuda_runtime.h>
#include <cuda_bf16.h>
#include <cstdint>

// out[b,s,d] = keep ? (emb[x[b,s],d] + pe[s,d]) * (1/0.9) : 0
// keep from JAX threefry2x32, partitionable mode:
//   per flat element i: key=(0,42), counter=(0,i), bits = out0 ^ out1
//   u = bitcast((bits>>9)|0x3f800000) - 1.0f ;  keep = u < 0.9f

__device__ __forceinline__ uint32_t tf_bits(uint32_t ctr) {
    const uint32_t ks0 = 0u;
    const uint32_t ks1 = 42u;
    const uint32_t ks2 = 0x1BD11BF0u;  // 0 ^ 42 ^ 0x1BD11BDA
    uint32_t x0 = ks0;        // counter hi = 0
    uint32_t x1 = ctr + ks1;  // counter lo = i
#define TF_R(r) { x0 += x1; x1 = __funnelshift_l(x1, x1, (r)); x1 ^= x0; }
    TF_R(13) TF_R(15) TF_R(26) TF_R(6)
    x0 += ks1; x1 += ks2 + 1u;
    TF_R(17) TF_R(29) TF_R(16) TF_R(24)
    x0 += ks2; x1 += ks0 + 2u;
    TF_R(13) TF_R(15) TF_R(26) TF_R(6)
    x0 += ks0; x1 += ks1 + 3u;
    TF_R(17) TF_R(29) TF_R(16) TF_R(24)
    x0 += ks1; x1 += ks2 + 4u;
    TF_R(13) TF_R(15) TF_R(26) TF_R(6)
    x0 += ks2; x1 += ks0 + 5u;
#undef TF_R
    return x0 ^ x1;
}

__device__ __forceinline__ float drop_apply(uint32_t bits, float v) {
    float u = __uint_as_float((bits >> 9) | 0x3f800000u) - 1.0f;
    return (u < 0.9f) ? v * (1.0f / 0.9f) : 0.0f;
}

// One block (256 threads, 4 elems/thread) covers exactly one (b,s) row of 1024.
__global__ __launch_bounds__(256) void embed_pe_drop_kernel(
    const int* __restrict__ x,
    const float* __restrict__ emb,
    float* __restrict__ out)
{
    const uint32_t j = (blockIdx.x * 256u + threadIdx.x) * 4u;  // flat elem idx
    const uint32_t d = j & 1023u;
    const uint32_t row = j >> 10;       // b*2048 + s, 0..16383
    const uint32_t s = row & 2047u;

    const int tok = __ldg(x + row);
    const float4 e = *reinterpret_cast<const float4*>(
        emb + (size_t)tok * 1024u + d);

    // pe[s, 2i] = sin(s * 10000^(-2i/1024)), pe[s, 2i+1] = cos(...)
    // inv_i = exp2(i * (-log2(10000)/512))
    const float kneg = -0.02595256324130752f;  // -log2(10000)/512
    const float fi0 = (float)(d >> 1);
    const float sf = (float)s;
    const float a0 = sf * exp2f(fi0 * kneg);
    const float a1 = sf * exp2f((fi0 + 1.0f) * kneg);
    float s0, c0, s1, c1;
    sincosf(a0, &s0, &c0);
    sincosf(a1, &s1, &c1);

    // 4 independent threefry chains (ILP)
    const uint32_t b0 = tf_bits(j);
    const uint32_t b1 = tf_bits(j + 1u);
    const uint32_t b2 = tf_bits(j + 2u);
    const uint32_t b3 = tf_bits(j + 3u);

    float4 y;
    y.x = drop_apply(b0, e.x + s0);
    y.y = drop_apply(b1, e.y + c0);
    y.z = drop_apply(b2, e.z + s1);
    y.w = drop_apply(b3, e.w + c1);

    *reinterpret_cast<float4*>(out + j) = y;
}

extern "C" void kernel_launch(void* const* d_in, const int* in_sizes, int n_in,
                              void* d_out, int out_size) {
    // Identify inputs by size: x has 8*2048 = 16384 elems; emb has 50257*1024.
    const int* x;
    const float* emb;
    if (in_sizes[0] == 8 * 2048) {
        x = (const int*)d_in[0];
        emb = (const float*)d_in[1];
    } else {
        x = (const int*)d_in[1];
        emb = (const float*)d_in[0];
    }
    float* out = (float*)d_out;

    const int total = 8 * 2048 * 1024;        // 16,777,216
    const int threads = 256;
    const int blocks = total / (threads * 4); // 16384

    embed_pe_drop_kernel<<<blocks, threads>>>(x, emb, out);
}

// round 2
// speedup vs baseline: 1.1134x; 1.1134x over previous
#include <cuda_runtime.h>
#include <cuda_bf16.h>
#include <cstdint>

// out[b,s,d] = keep ? (emb[x[b,s],d] + pe[s,d]) * (1/0.9) : 0
// keep from JAX threefry2x32 (partitionable): key=(0,42), ctr=(0,i),
// bits = out0^out1, keep <=> bits < 0xE6666600  (== u<0.9f exactly)

// Power-of-two multipliers for the IMAD.WIDE rotate trick, kept opaque in
// constant memory so ptxas cannot strength-reduce mul.wide back to shifts.
__constant__ uint32_t ROTM[4] = {1u << 13, 1u << 26, 1u << 17, 1u << 16};

__device__ __forceinline__ void R_shf(uint32_t& x0, uint32_t& x1, int r) {
    x0 += x1;
    x1 = __funnelshift_l(x1, x1, r) ^ x0;   // SHF + LOP3 (alu pipe)
}

__device__ __forceinline__ void R_wide(uint32_t& x0, uint32_t& x1, uint32_t m) {
    x0 += x1;
    unsigned long long p;
    asm("mul.wide.u32 %0, %1, %2;" : "=l"(p) : "r"(x1), "r"(m));  // IMAD.WIDE (fma pipe)
    x1 = ((uint32_t)p | (uint32_t)(p >> 32)) ^ x0;                // single LOP3
}

// One 4-round threefry group. Rotation sets alternate wide/shf to balance pipes.
#define TF_G1(x0, x1, mA, mB) { R_wide(x0,x1,mA); R_shf(x0,x1,15); R_wide(x0,x1,mB); R_shf(x0,x1,6); }
#define TF_G2(x0, x1, mA, mB) { R_wide(x0,x1,mA); R_shf(x0,x1,29); R_wide(x0,x1,mB); R_shf(x0,x1,24); }

__device__ __forceinline__ uint32_t tf_bits(uint32_t ctr,
                                            uint32_t m13, uint32_t m26,
                                            uint32_t m17, uint32_t m16) {
    const uint32_t ks0 = 0u;
    const uint32_t ks1 = 42u;
    const uint32_t ks2 = 0x1BD11BF0u;  // 0 ^ 42 ^ 0x1BD11BDA
    uint32_t x0 = ks0;
    uint32_t x1 = ctr + ks1;
    TF_G1(x0, x1, m13, m26)
    x0 += ks1; x1 += ks2 + 1u;
    TF_G2(x0, x1, m17, m16)
    x0 += ks2; x1 += ks0 + 2u;
    TF_G1(x0, x1, m13, m26)
    x0 += ks0; x1 += ks1 + 3u;
    TF_G2(x0, x1, m17, m16)
    x0 += ks1; x1 += ks2 + 4u;
    TF_G1(x0, x1, m13, m26)
    x0 += ks2; x1 += ks0 + 5u;
    return x0 ^ x1;
}

__device__ __forceinline__ float drop_apply(uint32_t bits, float v) {
    // keep  <=>  ((bits>>9)|0x3f800000) - 1.0f < 0.9f  <=>  bits < 0xE6666600
    return (bits < 0xE6666600u) ? v * (1.0f / 0.9f) : 0.0f;
}

// sin/cos of (turns * 2pi) via cheap turn reduction + MUFU
__device__ __forceinline__ void fast_sincos_turns(float t, float* s, float* c) {
    const float TWOPI = 6.2831853071795865f;
    float fr = t - rintf(t);           // [-0.5, 0.5] turns
    float a = fr * TWOPI;              // [-pi, pi]
    *s = __sinf(a);
    *c = __cosf(a);
}

// One block (256 threads, 4 elems/thread) covers one (b,s) row of 1024.
__global__ __launch_bounds__(256) void embed_pe_drop_kernel(
    const int* __restrict__ x,
    const float* __restrict__ emb,
    float* __restrict__ out)
{
    const uint32_t m13 = ROTM[0], m26 = ROTM[1], m17 = ROTM[2], m16 = ROTM[3];

    const uint32_t j = (blockIdx.x * 256u + threadIdx.x) * 4u;  // flat elem idx
    const uint32_t d = j & 1023u;
    const uint32_t row = j >> 10;       // b*2048 + s
    const uint32_t s = row & 2047u;

    const int tok = __ldg(x + row);
    const float4 e = *reinterpret_cast<const float4*>(
        emb + ((size_t)tok << 10) + d);

    // pe[s,2i]=sin(s*10000^(-2i/1024)), pe[s,2i+1]=cos(...)
    // angle in turns: t_i = s * 10000^(-i/512) / (2pi)
    const float KNEG   = -0.02595256324130752f;   // -log2(10000)/512
    const float STEP   = 0.98217188542871857f;    // 2^KNEG
    const float INV2PI = 0.15915494309189535f;
    const float fi0 = (float)(d >> 1);
    const float sf = (float)s;
    const float w0 = exp2f(fi0 * KNEG) * INV2PI;
    const float w1 = w0 * STEP;
    float s0, c0, s1, c1;
    fast_sincos_turns(sf * w0, &s0, &c0);
    fast_sincos_turns(sf * w1, &s1, &c1);

    // 4 independent threefry chains (ILP)
    const uint32_t b0 = tf_bits(j,      m13, m26, m17, m16);
    const uint32_t b1 = tf_bits(j + 1u, m13, m26, m17, m16);
    const uint32_t b2 = tf_bits(j + 2u, m13, m26, m17, m16);
    const uint32_t b3 = tf_bits(j + 3u, m13, m26, m17, m16);

    float4 y;
    y.x = drop_apply(b0, e.x + s0);
    y.y = drop_apply(b1, e.y + c0);
    y.z = drop_apply(b2, e.z + s1);
    y.w = drop_apply(b3, e.w + c1);

    *reinterpret_cast<float4*>(out + j) = y;
}

extern "C" void kernel_launch(void* const* d_in, const int* in_sizes, int n_in,
                              void* d_out, int out_size) {
    const int* x;
    const float* emb;
    if (in_sizes[0] == 8 * 2048) {
        x = (const int*)d_in[0];
        emb = (const float*)d_in[1];
    } else {
        x = (const int*)d_in[1];
        emb = (const float*)d_in[0];
    }
    float* out = (float*)d_out;

    const int total = 8 * 2048 * 1024;        // 16,777,216
    const int threads = 256;
    const int blocks = total / (threads * 4); // 16384

    embed_pe_drop_kernel<<<blocks, threads>>>(x, emb, out);
}